// round 4
// baseline (speedup 1.0000x reference)
#include <cuda_runtime.h>
#include <cuda_bf16.h>
#include <cfloat>
#include <math.h>

#define B_   32
#define T_   512
#define DIN  1024
#define DCB  256
#define KCB  8192
#define HMID 512
#define M_   (B_*T_)   // 16384
#define K3   (3*DCB)   // 768

typedef unsigned long long ull;
typedef unsigned int uint32;

// ---------------- scratch ------------------------------------------------------
__device__ float g_Y1[M_*HMID];
__device__ float g_Y2[M_*DCB];
__device__ float g_A3[M_*K3];
__device__ float g_Wc[DCB*K3];
__device__ float g_feat[M_*DCB];
__device__ float g_cnorm[KCB];
__device__ float g_rownorm[M_];
__device__ __nv_bfloat16 g_Fh[M_*DCB];
__device__ __nv_bfloat16 g_CBh[KCB*DCB];
__device__ uint32 g_rowmin_ord[M_];
__device__ ull   g_bestkey[M_];
__device__ int   g_idx[M_];
__device__ float g_quant[M_*DCB];
__device__ float g_xproj[M_*K3];
__device__ float g_whhT[DCB*K3];
__device__ float g_accum[2];

// ordered-uint encoding of float (monotonic)
__device__ __forceinline__ uint32 ford(float f) {
    uint32 b = __float_as_uint(f);
    return (b & 0x80000000u) ? ~b : (b | 0x80000000u);
}
__device__ __forceinline__ float iord(uint32 o) {
    uint32 b = (o & 0x80000000u) ? (o & 0x7FFFFFFFu) : ~o;
    return __uint_as_float(b);
}
__device__ __forceinline__ uint32 s2u(const void* p) {
    return (uint32)__cvta_generic_to_shared(p);
}

// ---------------- generic fp32 SIMT GEMM (round-2 proven):  C = act(A@B^T+b) ---
#define BM 128
#define BN 128
#define BKK 16
#define TM 8
#define TN 8

template<int RELU>
__global__ __launch_bounds__(256) void gemm_tn(
    const float* __restrict__ A, const float* __restrict__ B,
    const float* __restrict__ bias, float* __restrict__ C,
    int M, int N, int K)
{
    __shared__ float As[BKK][BM+4];
    __shared__ float Bs[BKK][BN+4];
    int tid = threadIdx.x;
    int tr = tid >> 4, tc = tid & 15;
    int m0 = blockIdx.y * BM, n0 = blockIdx.x * BN;
    float acc[TM][TN];
    #pragma unroll
    for (int i = 0; i < TM; i++)
        #pragma unroll
        for (int j = 0; j < TN; j++) acc[i][j] = 0.f;

    for (int k0 = 0; k0 < K; k0 += BKK) {
        #pragma unroll
        for (int it = 0; it < 2; it++) {
            int id = tid + it*256;
            int row = id >> 2;
            int kq  = (id & 3) << 2;
            float4 v = *(const float4*)&A[(size_t)(m0+row)*K + k0 + kq];
            As[kq+0][row] = v.x; As[kq+1][row] = v.y;
            As[kq+2][row] = v.z; As[kq+3][row] = v.w;
        }
        #pragma unroll
        for (int it = 0; it < 2; it++) {
            int id = tid + it*256;
            int row = id >> 2;
            int kq  = (id & 3) << 2;
            float4 v = *(const float4*)&B[(size_t)(n0+row)*K + k0 + kq];
            Bs[kq+0][row] = v.x; Bs[kq+1][row] = v.y;
            Bs[kq+2][row] = v.z; Bs[kq+3][row] = v.w;
        }
        __syncthreads();
        #pragma unroll
        for (int kk = 0; kk < BKK; kk++) {
            float ra[TM], rb[TN];
            #pragma unroll
            for (int i = 0; i < TM; i++) ra[i] = As[kk][tr*TM+i];
            #pragma unroll
            for (int j = 0; j < TN; j++) rb[j] = Bs[kk][tc*TN+j];
            #pragma unroll
            for (int i = 0; i < TM; i++)
                #pragma unroll
                for (int j = 0; j < TN; j++)
                    acc[i][j] = __fmaf_rn(ra[i], rb[j], acc[i][j]);
        }
        __syncthreads();
    }
    #pragma unroll
    for (int i = 0; i < TM; i++) {
        int m = m0 + tr*TM + i;
        #pragma unroll
        for (int j = 0; j < TN; j++) {
            int n = n0 + tc*TN + j;
            float v = __fadd_rn(acc[i][j], bias[n]);
            if (RELU) v = fmaxf(v, 0.f);
            C[(size_t)m*N + n] = v;
        }
    }
}

// ---------------- small prep kernels ------------------------------------------
__global__ void init_misc() {
    int i = blockIdx.x*blockDim.x + threadIdx.x;
    if (i < 2) g_accum[i] = 0.f;
    if (i < M_) { g_rowmin_ord[i] = 0xFFFFFFFFu; g_bestkey[i] = 0xFFFFFFFFFFFFFFFFull; }
}

__global__ void prep_wc(const float* __restrict__ conv_w) {
    int o = blockIdx.x*blockDim.x + threadIdx.x;
    if (o >= DCB*K3) return;
    int c = o / K3, r = o % K3, k = r / DCB, i = r % DCB;
    g_Wc[o] = conv_w[((size_t)c*DCB + i)*3 + k];
}

__global__ void transpose_whh(const float* __restrict__ whh) {
    int o = blockIdx.x*blockDim.x + threadIdx.x;
    if (o >= DCB*K3) return;
    int d = o / K3, j = o % K3;
    g_whhT[o] = whh[(size_t)j*DCB + d];
}

__global__ void im2col_k() {
    int stride = gridDim.x * blockDim.x;
    for (int o = blockIdx.x*blockDim.x + threadIdx.x; o < M_*K3; o += stride) {
        int m = o / K3, r = o % K3, k = r / DCB, i = r % DCB;
        int b = m >> 9, t = m & 511;
        int tt = t + k - 1;
        g_A3[o] = (tt >= 0 && tt < T_) ? g_Y2[((size_t)(b*T_ + tt))*DCB + i] : 0.f;
    }
}

// sequential scalar sum of squares (mul then add, no FMA) — bit-matches reference.
__global__ void cnorm_k(const float* __restrict__ CB) {
    int k = blockIdx.x*blockDim.x + threadIdx.x;
    if (k >= KCB) return;
    const float* row = CB + (size_t)k*DCB;
    float a = 0.f;
    for (int d = 0; d < DCB; d++) {
        float v = row[d];
        a = __fadd_rn(a, __fmul_rn(v, v));
    }
    g_cnorm[k] = a;
}

__global__ void rownorm_k() {
    int m = blockIdx.x*blockDim.x + threadIdx.x;
    if (m >= M_) return;
    const float* row = g_feat + (size_t)m*DCB;
    float a = 0.f;
    for (int d = 0; d < DCB; d++) {
        float v = row[d];
        a = __fadd_rn(a, __fmul_rn(v, v));
    }
    g_rownorm[m] = a;
}

__global__ void f2h_k() {
    int i = blockIdx.x*blockDim.x + threadIdx.x;
    if (i < M_*DCB) g_Fh[i] = __float2bfloat16_rn(g_feat[i]);
}
__global__ void cb2h_k(const float* __restrict__ CB) {
    int i = blockIdx.x*blockDim.x + threadIdx.x;
    if (i < KCB*DCB) g_CBh[i] = __float2bfloat16_rn(CB[i]);
}

// ---------------- VQ: bf16 HMMA prepass + exact rescore -------------------------
// Block: 256 thr (8 warps), tile 128 M x 128 N, K=256 in chunks of 32.
// Warp grid 4x2: warp tile 32M x 64N.
// PASS 1: per-row approx min -> g_rowmin_ord. PASS 2: identical recompute; any
// s_approx <= rowmin+margin gets exact fp32 chain rescore -> g_bestkey atomicMin.
template<int PASS>
__global__ __launch_bounds__(256) void vq_mma(
    const float* __restrict__ CBfp)
{
    __shared__ __align__(16) __nv_bfloat16 As[128][40];
    __shared__ __align__(16) __nv_bfloat16 Bs[128][40];
    int tid = threadIdx.x;
    int warp = tid >> 5, lane = tid & 31;
    int wm = warp & 3, wn = warp >> 2;
    int m0 = blockIdx.x * 128, n0 = blockIdx.y * 128;
    int g = lane >> 2, t = lane & 3;

    float d[2][8][4];
    #pragma unroll
    for (int mt = 0; mt < 2; mt++)
        #pragma unroll
        for (int nt = 0; nt < 8; nt++)
            #pragma unroll
            for (int e = 0; e < 4; e++) d[mt][nt][e] = 0.f;

    uint32 asbase = s2u(&As[0][0]);
    uint32 bsbase = s2u(&Bs[0][0]);

    for (int k0 = 0; k0 < DCB; k0 += 32) {
        // load 128x32 bf16 tiles (64B/row, 4x16B chunks, 2 per thread)
        #pragma unroll
        for (int p = 0; p < 2; p++) {
            int id = tid + p*256;
            int row = id >> 2, ch = id & 3;
            *(uint4*)((char*)&As[0][0] + row*80 + ch*16) =
                *(const uint4*)&g_Fh[(size_t)(m0+row)*DCB + k0 + ch*8];
            *(uint4*)((char*)&Bs[0][0] + row*80 + ch*16) =
                *(const uint4*)&g_CBh[(size_t)(n0+row)*DCB + k0 + ch*8];
        }
        __syncthreads();
        #pragma unroll
        for (int kk = 0; kk < 2; kk++) {
            int colb = (kk*16 + (lane >> 4)*8) * 2;   // byte offset of k-col
            int r15 = lane & 15;
            uint32 a[2][4];
            #pragma unroll
            for (int mt = 0; mt < 2; mt++) {
                uint32 addr = asbase + (wm*32 + mt*16 + r15)*80 + colb;
                asm volatile("ldmatrix.sync.aligned.m8n8.x4.shared.b16 {%0,%1,%2,%3}, [%4];"
                    : "=r"(a[mt][0]), "=r"(a[mt][1]), "=r"(a[mt][2]), "=r"(a[mt][3])
                    : "r"(addr));
            }
            uint32 b[4][4];
            #pragma unroll
            for (int gq = 0; gq < 4; gq++) {
                uint32 addr = bsbase + (wn*64 + gq*16 + r15)*80 + colb;
                asm volatile("ldmatrix.sync.aligned.m8n8.x4.shared.b16 {%0,%1,%2,%3}, [%4];"
                    : "=r"(b[gq][0]), "=r"(b[gq][1]), "=r"(b[gq][2]), "=r"(b[gq][3])
                    : "r"(addr));
            }
            #pragma unroll
            for (int mt = 0; mt < 2; mt++)
                #pragma unroll
                for (int nt = 0; nt < 8; nt++) {
                    int gq = nt >> 1, wh = nt & 1;
                    asm volatile(
                        "mma.sync.aligned.m16n8k16.row.col.f32.bf16.bf16.f32 "
                        "{%0,%1,%2,%3}, {%4,%5,%6,%7}, {%8,%9}, {%0,%1,%2,%3};"
                        : "+f"(d[mt][nt][0]), "+f"(d[mt][nt][1]),
                          "+f"(d[mt][nt][2]), "+f"(d[mt][nt][3])
                        : "r"(a[mt][0]), "r"(a[mt][1]), "r"(a[mt][2]), "r"(a[mt][3]),
                          "r"(b[gq][wh]), "r"(b[gq][2+wh]));
                }
        }
        __syncthreads();
    }

    // epilogue
    int nbase = n0 + wn*64;
    float cnv[8][2];
    #pragma unroll
    for (int nt = 0; nt < 8; nt++) {
        int n = nbase + nt*8 + t*2;
        cnv[nt][0] = g_cnorm[n];
        cnv[nt][1] = g_cnorm[n+1];
    }
    #pragma unroll
    for (int mt = 0; mt < 2; mt++) {
        #pragma unroll
        for (int half = 0; half < 2; half++) {
            int m = m0 + wm*32 + mt*16 + g + half*8;
            if (PASS == 1) {
                float mn = FLT_MAX;
                #pragma unroll
                for (int nt = 0; nt < 8; nt++) {
                    float s0 = cnv[nt][0] - 2.f*d[mt][nt][half*2+0];
                    float s1 = cnv[nt][1] - 2.f*d[mt][nt][half*2+1];
                    mn = fminf(mn, fminf(s0, s1));
                }
                mn = fminf(mn, __shfl_xor_sync(0xffffffffu, mn, 1));
                mn = fminf(mn, __shfl_xor_sync(0xffffffffu, mn, 2));
                if (t == 0) atomicMin(&g_rowmin_ord[m], ford(mn));
            } else {
                float A = g_rownorm[m];
                float thr = iord(g_rowmin_ord[m]) + (7.5e-5f + 3.5e-5f*sqrtf(A));
                #pragma unroll
                for (int nt = 0; nt < 8; nt++) {
                    #pragma unroll
                    for (int e = 0; e < 2; e++) {
                        float s = cnv[nt][e] - 2.f*d[mt][nt][half*2+e];
                        if (s <= thr) {
                            int n = nbase + nt*8 + t*2 + e;
                            const float* fr = g_feat + (size_t)m*DCB;
                            const float* cr = CBfp + (size_t)n*DCB;
                            float p = 0.f;
                            #pragma unroll 8
                            for (int k = 0; k < DCB; k++)
                                p = __fmaf_rn(fr[k], cr[k], p);
                            float se = __fadd_rn(__fadd_rn(A, -__fmul_rn(2.f, p)),
                                                 g_cnorm[n]);
                            ull key = ((ull)ford(se) << 32) | (uint32)n;
                            atomicMin(&g_bestkey[m], key);
                        }
                    }
                }
            }
        }
    }
}

__global__ void vq_extract(float* __restrict__ out) {
    int m = blockIdx.x*blockDim.x + threadIdx.x;
    if (m >= M_) return;
    int idx = (int)(g_bestkey[m] & 0xFFFFFFFFull);
    g_idx[m] = idx;
    out[m] = (float)idx;
}

__global__ void quant_mse(const float* __restrict__ CB, float* __restrict__ out) {
    int m = blockIdx.x, c = threadIdx.x;
    int id = g_idx[m];
    float q = CB[(size_t)id*DCB + c];
    g_quant[(size_t)m*DCB + c] = q;
    out[M_ + (size_t)m*DCB + c] = q;
    float d = g_feat[(size_t)m*DCB + c] - q;
    float s = d*d;
    #pragma unroll
    for (int off = 16; off; off >>= 1) s += __shfl_down_sync(0xffffffffu, s, off);
    __shared__ float red[8];
    if ((c & 31) == 0) red[c >> 5] = s;
    __syncthreads();
    if (c == 0) {
        float tt = 0.f;
        #pragma unroll
        for (int w = 0; w < 8; w++) tt += red[w];
        atomicAdd(&g_accum[0], tt);
    }
}

// ---------------- GRU (round-2 proven) -----------------------------------------
__global__ __launch_bounds__(768) void gru_kernel(const float* __restrict__ bhh) {
    int b = blockIdx.x;
    int tid = threadIdx.x;
    int ds = tid / 192;
    int jj = tid % 192;
    __shared__ float sh_h[DCB];
    __shared__ float sh_gh[K3];
    __shared__ float part[4][K3];
    if (tid < DCB) sh_h[tid] = 0.f;
    float bv0=0,bv1=0,bv2=0,bv3=0;
    if (ds == 0) { bv0=bhh[jj*4]; bv1=bhh[jj*4+1]; bv2=bhh[jj*4+2]; bv3=bhh[jj*4+3]; }
    const float* wbase = g_whhT + (size_t)(ds*64)*K3 + jj*4;
    float ctxsum = 0.f;
    __syncthreads();

    for (int t = 0; t < T_-1; t++) {
        float ax=0.f, ay=0.f, az=0.f, aw=0.f;
        const float* wp = wbase;
        const float* hp = sh_h + ds*64;
        #pragma unroll 8
        for (int d = 0; d < 64; d++) {
            float hv = hp[d];
            float4 w = *(const float4*)wp;
            ax = fmaf(hv, w.x, ax); ay = fmaf(hv, w.y, ay);
            az = fmaf(hv, w.z, az); aw = fmaf(hv, w.w, aw);
            wp += K3;
        }
        part[ds][jj*4+0]=ax; part[ds][jj*4+1]=ay; part[ds][jj*4+2]=az; part[ds][jj*4+3]=aw;
        __syncthreads();
        if (ds == 0) {
            int o = jj*4;
            sh_gh[o+0] = part[0][o+0]+part[1][o+0]+part[2][o+0]+part[3][o+0] + bv0;
            sh_gh[o+1] = part[0][o+1]+part[1][o+1]+part[2][o+1]+part[3][o+1] + bv1;
            sh_gh[o+2] = part[0][o+2]+part[1][o+2]+part[2][o+2]+part[3][o+2] + bv2;
            sh_gh[o+3] = part[0][o+3]+part[1][o+3]+part[2][o+3]+part[3][o+3] + bv3;
        }
        __syncthreads();
        if (tid < DCB) {
            int j = tid;
            const float* xp = g_xproj + ((size_t)b*T_ + t)*K3;
            float r = 1.f/(1.f + expf(-(xp[j]       + sh_gh[j])));
            float z = 1.f/(1.f + expf(-(xp[DCB+j]   + sh_gh[DCB+j])));
            float n = tanhf(xp[2*DCB+j] + r*sh_gh[2*DCB+j]);
            float hprev = sh_h[j];
            float hnew = (1.f - z)*n + z*hprev;
            float dl = hnew - g_feat[((size_t)b*T_ + t + 1)*DCB + j];
            ctxsum = fmaf(dl, dl, ctxsum);
            sh_h[j] = hnew;
        }
        __syncthreads();
    }
    #pragma unroll
    for (int off = 16; off; off >>= 1) ctxsum += __shfl_down_sync(0xffffffffu, ctxsum, off);
    __shared__ float wsum[24];
    if ((tid & 31) == 0) wsum[tid >> 5] = ctxsum;
    __syncthreads();
    if (tid == 0) {
        float s = 0.f;
        #pragma unroll
        for (int w = 0; w < 24; w++) s += wsum[w];
        atomicAdd(&g_accum[1], s);
    }
}

__global__ void finalize_k(float* __restrict__ out) {
    float mse = g_accum[0] / 4194304.0f;
    float ctx = g_accum[1] / 4186112.0f;
    size_t base = (size_t)M_ + (size_t)M_*DCB;
    out[base+0] = mse;
    out[base+1] = mse;
    out[base+2] = ctx;
    out[base+3] = 1.25f*mse + 0.1f*ctx;
}

// ---------------- launch --------------------------------------------------------
extern "C" void kernel_launch(void* const* d_in, const int* in_sizes, int n_in,
                              void* d_out, int out_size) {
    const float* x      = (const float*)d_in[0];
    const float* w1     = (const float*)d_in[1];
    const float* b1     = (const float*)d_in[2];
    const float* w2     = (const float*)d_in[3];
    const float* b2     = (const float*)d_in[4];
    const float* conv_w = (const float*)d_in[5];
    const float* conv_b = (const float*)d_in[6];
    const float* cb     = (const float*)d_in[7];
    const float* wih    = (const float*)d_in[8];
    const float* whh    = (const float*)d_in[9];
    const float* bih    = (const float*)d_in[10];
    const float* bhh    = (const float*)d_in[11];
    float* out = (float*)d_out;

    float *pY1, *pY2, *pA3, *pWc, *pF, *pQ, *pXp;
    cudaGetSymbolAddress((void**)&pY1, g_Y1);
    cudaGetSymbolAddress((void**)&pY2, g_Y2);
    cudaGetSymbolAddress((void**)&pA3, g_A3);
    cudaGetSymbolAddress((void**)&pWc, g_Wc);
    cudaGetSymbolAddress((void**)&pF,  g_feat);
    cudaGetSymbolAddress((void**)&pQ,  g_quant);
    cudaGetSymbolAddress((void**)&pXp, g_xproj);

    init_misc<<<(M_+255)/256, 256>>>();

    gemm_tn<1><<<dim3(HMID/BN, M_/BM), 256>>>(x,   w1, b1, pY1, M_, HMID, DIN);
    gemm_tn<1><<<dim3(DCB/BN,  M_/BM), 256>>>(pY1, w2, b2, pY2, M_, DCB, HMID);

    prep_wc<<<(DCB*K3+255)/256, 256>>>(conv_w);
    im2col_k<<<4096, 256>>>();
    gemm_tn<0><<<dim3(DCB/BN, M_/BM), 256>>>(pA3, pWc, conv_b, pF, M_, DCB, K3);

    cnorm_k<<<KCB/256, 256>>>(cb);
    rownorm_k<<<M_/256, 256>>>();
    f2h_k<<<(M_*DCB+255)/256, 256>>>();
    cb2h_k<<<(KCB*DCB+255)/256, 256>>>(cb);

    vq_mma<1><<<dim3(M_/128, KCB/128), 256>>>(cb);
    vq_mma<2><<<dim3(M_/128, KCB/128), 256>>>(cb);
    vq_extract<<<M_/256, 256>>>(out);
    quant_mse<<<M_, 256>>>(cb, out);

    gemm_tn<0><<<dim3(K3/BN, M_/BM), 256>>>(pQ, wih, bih, pXp, M_, K3, DCB);
    transpose_whh<<<(DCB*K3+255)/256, 256>>>(whh);
    gru_kernel<<<B_, 768>>>(bhh);

    finalize_k<<<1, 1>>>(out);
}